// round 16
// baseline (speedup 1.0000x reference)
#include <cuda_runtime.h>
#include <cuda_fp16.h>
#include <cstdint>
#include <math.h>

// out = GELU_exact(x @ W.T + b)
// R16: fp16 single-term mma.sync GEMM, 64x64 tiles / 1024 CTAs (R15) with
// BK=128 (256B rows) and a 2-stage ring -> 4 barriers + 4 cp.async groups
// instead of 8. Stage load (kt+1) overlaps consumption (kt).

#define NN 8192
#define KK 512
#define OO 512

#define BM 64
#define BN 64
#define BK 128                   // fp16 elems per k-tile (256 B/row)
#define NKT (KK / BK)            // 4
#define THREADS 128

#define ST_B   16384             // stage: A[64x256B] 16K | B 16K
#define STAGE  32768
#define NSTAGE 2
#define SMEM_TOTAL (NSTAGE * STAGE)   // 64 KB -> occ 3

__device__ __align__(128) __half g_xh[NN * KK];   // 8 MB
__device__ __align__(128) __half g_wh[OO * KK];   // 0.5 MB

__device__ __forceinline__ uint32_t smem_u32(const void* p) {
    uint32_t a;
    asm("{ .reg .u64 t; cvta.to.shared.u64 t, %1; cvt.u32.u64 %0, t; }" : "=r"(a) : "l"(p));
    return a;
}

#define CP16(dst, src) \
    asm volatile("cp.async.cg.shared.global [%0], [%1], 16;" :: "r"(dst), "l"(src) : "memory")
#define CP_COMMIT() asm volatile("cp.async.commit_group;" ::: "memory")
#define CP_WAIT0()  asm volatile("cp.async.wait_group 0;" ::: "memory")

__device__ __forceinline__ void ldm4(uint32_t* r, uint32_t addr) {
    asm volatile("ldmatrix.sync.aligned.m8n8.x4.shared.b16 {%0,%1,%2,%3}, [%4];"
                 : "=r"(r[0]), "=r"(r[1]), "=r"(r[2]), "=r"(r[3]) : "r"(addr));
}

__device__ __forceinline__ void mma_f16(float* d, const uint32_t* a, const uint32_t* b) {
    asm volatile(
        "mma.sync.aligned.m16n8k16.row.col.f32.f16.f16.f32 "
        "{%0,%1,%2,%3}, {%4,%5,%6,%7}, {%8,%9}, {%0,%1,%2,%3};"
        : "+f"(d[0]), "+f"(d[1]), "+f"(d[2]), "+f"(d[3])
        : "r"(a[0]), "r"(a[1]), "r"(a[2]), "r"(a[3]), "r"(b[0]), "r"(b[1]));
}

__device__ __forceinline__ uint32_t packh2(float a, float b) {
    __half2 h = __floats2half2_rn(a, b);
    return *(uint32_t*)&h;
}

// swizzled byte offset in a 256B-row tile: row r, 16B-chunk c (0..15).
// 128B-swizzle applied within each 128B half of the row.
__device__ __forceinline__ uint32_t swz16(int r, int c) {
    return (uint32_t)(r * 256 + ((((c & 7) ^ (r & 7))) << 4) + ((c >> 3) << 7));
}

// A&S 7.1.26 erf (abs err 1.5e-7)
__device__ __forceinline__ float gelu_f(float h) {
    float s = h * 0.70710678118654752f;
    float a = fabsf(s);
    float t = __frcp_rn(fmaf(0.3275911f, a, 1.0f));
    float p = fmaf(fmaf(fmaf(fmaf(1.061405429f, t, -1.453152027f), t, 1.421413741f),
                        t, -0.284496736f), t, 0.254829592f) * t;
    float e = __expf(-a * a);
    float erfv = fmaf(-p, e, 1.0f);
    erfv = copysignf(erfv, s);
    return 0.5f * h * (1.0f + erfv);
}

// ---------------- pack kernel: f32 -> fp16 (rne), x and W ----------------
__global__ __launch_bounds__(256) void pack_kernel(const float* __restrict__ x,
                                                   const float* __restrict__ W) {
    const int g = blockIdx.x * 256 + threadIdx.x;
    const int A_GROUPS = NN * (KK / 8);
    const float* src;
    __half* dst;
    if (g < A_GROUPS) {
        src = x + (size_t)g * 8;
        dst = g_xh + (size_t)g * 8;
    } else {
        size_t g2 = (size_t)(g - A_GROUPS);
        src = W + g2 * 8;
        dst = g_wh + g2 * 8;
    }
    float4 v0 = *(const float4*)src;
    float4 v1 = *(const float4*)(src + 4);
    uint4 o;
    o.x = packh2(v0.x, v0.y);
    o.y = packh2(v0.z, v0.w);
    o.z = packh2(v1.x, v1.y);
    o.w = packh2(v1.z, v1.w);
    *(uint4*)dst = o;
}

// ---------------- main GEMM kernel ----------------
__global__ __launch_bounds__(THREADS, 3)
void gemm_f16_kernel(const float* __restrict__ bias, float* __restrict__ C) {
    extern __shared__ uint8_t smem[];
    const uint32_t S = smem_u32(smem);
    const int tid = threadIdx.x;
    const int l = tid & 31, wid = tid >> 5;
    const int mwarp = wid & 1;   // 2 M-warps of 32 rows
    const int nwarp = wid >> 1;  // 2 N-warps of 32 cols
    const int mb = blockIdx.x, nb = blockIdx.y;

    // ---- hoisted loader addressing: 64 rows x 16 chunks = 1024 slots per
    // operand; 128 threads -> 8 A-chunks + 8 B-chunks each ----
    uint32_t s_dstA[8], s_dstB[8];
    const uint8_t *gA[8], *gB[8];
#pragma unroll
    for (int j = 0; j < 8; j++) {
        int slot = tid + j * 128;
        int r = slot >> 4, c = slot & 15;
        s_dstA[j] = swz16(r, c);
        s_dstB[j] = ST_B + swz16(r, c);
        gA[j] = (const uint8_t*)(g_xh + (size_t)(mb * BM + r) * KK + c * 8);
        gB[j] = (const uint8_t*)(g_wh + (size_t)(nb * BN + r) * KK + c * 8);
    }

    // ---- hoisted ldmatrix bases ----
    // slice ks (0..7): addr = (base ^ (((2ks)&7)<<4)) + (ks>>2)*128
    const int a_r = ((l >> 3) & 1) * 8 + (l & 7);
    const int a_cs = (l >> 4) & 1;
    const int b_n = ((l >> 4) & 1) * 8 + (l & 7);
    const int b_cs = (l >> 3) & 1;
    uint32_t baseA[2], baseB[2];
#pragma unroll
    for (int mf = 0; mf < 2; mf++) baseA[mf] = swz16(mwarp * 32 + mf * 16 + a_r, a_cs);
#pragma unroll
    for (int nf2 = 0; nf2 < 2; nf2++) baseB[nf2] = ST_B + swz16(nwarp * 32 + nf2 * 16 + b_n, b_cs);

    float acc[2][4][4];
#pragma unroll
    for (int i = 0; i < 2; i++)
#pragma unroll
        for (int j = 0; j < 4; j++)
#pragma unroll
            for (int k = 0; k < 4; k++) acc[i][j][k] = 0.0f;

    // prologue: stage 0 (kt 0)
#pragma unroll
    for (int j = 0; j < 8; j++) {
        CP16(S + s_dstA[j], gA[j]);
        CP16(S + s_dstB[j], gB[j]);
    }
    CP_COMMIT();

    for (int kt = 0; kt < NKT; kt++) {
        CP_WAIT0();        // stage kt%2 data ready
        __syncthreads();   // everyone done reading stage (kt+1)%2 from iter kt-1
        if (kt + 1 < NKT) {
            const uint32_t st = S + ((kt + 1) & 1) * STAGE;
            const uint32_t go = (uint32_t)(kt + 1) * 256;
#pragma unroll
            for (int j = 0; j < 8; j++) {
                CP16(st + s_dstA[j], gA[j] + go);
                CP16(st + s_dstB[j], gB[j] + go);
            }
            CP_COMMIT();
        }
        const uint32_t stg = S + (kt & 1) * STAGE;

        // B-fragment double buffer across the 8 k16 slices; A inline
        uint32_t Bf[2][8];
#pragma unroll
        for (int nf2 = 0; nf2 < 2; nf2++)
            ldm4(&Bf[0][nf2 * 4], stg + baseB[nf2]);

#pragma unroll
        for (int ks = 0; ks < 8; ks++) {
            const int cur = ks & 1, nxt = cur ^ 1;
            if (ks < 7) {
                const uint32_t nlo = (uint32_t)((2 * (ks + 1)) & 7) << 4;
                const uint32_t nhi = (uint32_t)((ks + 1) >> 2) << 7;
#pragma unroll
                for (int nf2 = 0; nf2 < 2; nf2++)
                    ldm4(&Bf[nxt][nf2 * 4], (stg + (baseB[nf2] ^ nlo)) + nhi);
            }
            const uint32_t klo = (uint32_t)((2 * ks) & 7) << 4;
            const uint32_t khi = (uint32_t)(ks >> 2) << 7;
#pragma unroll
            for (int mf = 0; mf < 2; mf++) {
                uint32_t A[4];
                ldm4(A, (stg + (baseA[mf] ^ klo)) + khi);
#pragma unroll
                for (int nf = 0; nf < 4; nf++)
                    mma_f16(acc[mf][nf], A, &Bf[cur][nf * 2]);
            }
        }
    }

    // epilogue: bias + GELU
#pragma unroll
    for (int mf = 0; mf < 2; mf++) {
#pragma unroll
        for (int nf = 0; nf < 4; nf++) {
            int m0 = mb * BM + mwarp * 32 + mf * 16 + (l >> 2);
            int n0 = nb * BN + nwarp * 32 + nf * 8 + 2 * (l & 3);
            float b0 = __ldg(&bias[n0]);
            float b1 = __ldg(&bias[n0 + 1]);
            float2 v0, v1;
            v0.x = gelu_f(acc[mf][nf][0] + b0);
            v0.y = gelu_f(acc[mf][nf][1] + b1);
            v1.x = gelu_f(acc[mf][nf][2] + b0);
            v1.y = gelu_f(acc[mf][nf][3] + b1);
            *(float2*)&C[(size_t)m0 * OO + n0] = v0;
            *(float2*)&C[(size_t)(m0 + 8) * OO + n0] = v1;
        }
    }
}

// ---------------- launch ----------------
extern "C" void kernel_launch(void* const* d_in, const int* in_sizes, int n_in,
                              void* d_out, int out_size) {
    const float* x = (const float*)d_in[0];
    const float* W = (const float*)d_in[2];
    const float* b = (const float*)d_in[3];
    float* out = (float*)d_out;

    cudaFuncSetAttribute(gemm_f16_kernel,
                         cudaFuncAttributeMaxDynamicSharedMemorySize, SMEM_TOTAL);

    const int A_GROUPS = NN * (KK / 8);
    const int B_GROUPS = OO * (KK / 8);
    pack_kernel<<<(A_GROUPS + B_GROUPS) / 256, 256>>>(x, W);

    dim3 grid(NN / BM, OO / BN);  // (128, 8) = 1024 CTAs
    gemm_f16_kernel<<<grid, THREADS, SMEM_TOTAL>>>(b, out);
}